// round 1
// baseline (speedup 1.0000x reference)
#include <cuda_runtime.h>
#include <cuda_bf16.h>
#include <cstdint>

#define FEAT 64
#define KMAX 2048
#define CHUNK 128
#define SSTRIDE 132   // 132 % 4 == 0 -> 16B-aligned float4 rows; bank conflicts bounded (8-way) on transpose writes only

// Scratch (no allocations allowed): segment sums, counts, centroid norms.
__device__ float g_sums[KMAX * FEAT];
__device__ float g_counts[KMAX];
__device__ float g_cnorm[KMAX];

// ---- packed f32x2 helpers (Blackwell FFMA2 path) ----
__device__ __forceinline__ unsigned long long pack_dup(float v) {
    unsigned long long r;
    asm("mov.b64 %0, {%1, %1};" : "=l"(r) : "r"(__float_as_uint(v)));
    return r;
}
__device__ __forceinline__ unsigned long long fma2(unsigned long long a,
                                                   unsigned long long b,
                                                   unsigned long long c) {
    unsigned long long d;
    asm("fma.rn.f32x2 %0, %1, %2, %3;" : "=l"(d) : "l"(a), "l"(b), "l"(c));
    return d;
}
__device__ __forceinline__ void unpack2(unsigned long long p, float& lo, float& hi) {
    unsigned int a, b;
    asm("mov.b64 {%0, %1}, %2;" : "=r"(a), "=r"(b) : "l"(p));
    lo = __uint_as_float(a);
    hi = __uint_as_float(b);
}

// K0: zero scratch + compute ||c||^2
__global__ void init_kernel(const float* __restrict__ cent, int K) {
    int idx = blockIdx.x * blockDim.x + threadIdx.x;
    if (idx < K * FEAT) g_sums[idx] = 0.0f;
    if (idx < K) {
        g_counts[idx] = 0.0f;
        float s = 0.0f;
        const float4* row = reinterpret_cast<const float4*>(cent + (size_t)idx * FEAT);
#pragma unroll
        for (int q = 0; q < FEAT / 4; q++) {
            float4 v = row[q];
            s += v.x * v.x + v.y * v.y + v.z * v.z + v.w * v.w;
        }
        g_cnorm[idx] = s;
    }
}

// K1: assignment (argmin over K of ||c||^2 - 2 x.c) + fused scatter into g_sums/g_counts.
__global__ void __launch_bounds__(256, 2)
assign_scatter_kernel(const float* __restrict__ x,
                      const float* __restrict__ cent,
                      float* __restrict__ out_assign,  // may be null
                      int N, int K) {
    __shared__ float csm[FEAT * SSTRIDE];  // transposed chunk: csm[k*SSTRIDE + j]
    __shared__ float cnsm[CHUNK];

    const int i = blockIdx.x * 256 + threadIdx.x;

    // Load this thread's point into registers.
    float xr[FEAT];
    if (i < N) {
        const float4* xv = reinterpret_cast<const float4*>(x + (size_t)i * FEAT);
#pragma unroll
        for (int q = 0; q < FEAT / 4; q++) {
            float4 v = xv[q];
            xr[4 * q + 0] = v.x; xr[4 * q + 1] = v.y;
            xr[4 * q + 2] = v.z; xr[4 * q + 3] = v.w;
        }
    } else {
#pragma unroll
        for (int q = 0; q < FEAT; q++) xr[q] = 0.0f;
    }

    float best = 3.4e38f;
    int bestj = 0;

    for (int c0 = 0; c0 < K; c0 += CHUNK) {
        __syncthreads();
        // Coalesced global read, transposed shared write.
        for (int idx = threadIdx.x; idx < CHUNK * FEAT; idx += 256) {
            int j = idx >> 6;        // centroid within chunk
            int k = idx & (FEAT - 1);
            csm[k * SSTRIDE + j] = cent[(size_t)(c0 + j) * FEAT + k];
        }
        if (threadIdx.x < CHUNK) cnsm[threadIdx.x] = g_cnorm[c0 + threadIdx.x];
        __syncthreads();

        // 8 centroids at a time; 4 packed f32x2 accumulators.
        for (int j = 0; j < CHUNK; j += 8) {
            unsigned long long a0 = 0ull, a1 = 0ull, a2 = 0ull, a3 = 0ull;
#pragma unroll
            for (int k = 0; k < FEAT; k++) {
                unsigned long long xp = pack_dup(xr[k]);
                const ulonglong2* row =
                    reinterpret_cast<const ulonglong2*>(csm + k * SSTRIDE + j);
                ulonglong2 p = row[0];   // centroids j..j+3 at feature k
                ulonglong2 q = row[1];   // centroids j+4..j+7 at feature k
                a0 = fma2(xp, p.x, a0);
                a1 = fma2(xp, p.y, a1);
                a2 = fma2(xp, q.x, a2);
                a3 = fma2(xp, q.y, a3);
            }
            float d[8];
            unpack2(a0, d[0], d[1]);
            unpack2(a1, d[2], d[3]);
            unpack2(a2, d[4], d[5]);
            unpack2(a3, d[6], d[7]);
#pragma unroll
            for (int t = 0; t < 8; t++) {
                float score = cnsm[j + t] - 2.0f * d[t];
                if (score < best) { best = score; bestj = c0 + j + t; }
            }
        }
    }

    if (i < N) {
        if (out_assign) out_assign[i] = (float)bestj;
        // Fused scatter: x is already in registers.
        atomicAdd(&g_counts[bestj], 1.0f);
        float* srow = g_sums + (size_t)bestj * FEAT;
#pragma unroll
        for (int k = 0; k < FEAT; k++) atomicAdd(&srow[k], xr[k]);
    }
}

// K2: EMA update of centroids.
__global__ void finalize_kernel(const float* __restrict__ cent,
                                float* __restrict__ out_cent, int K) {
    int idx = blockIdx.x * blockDim.x + threadIdx.x;
    if (idx >= K * FEAT) return;
    int k = idx >> 6;
    float cnt = g_counts[k];
    float c = cent[idx];
    float mean = g_sums[idx] / fmaxf(cnt, 1.0f);
    float nc = (cnt > 0.0f) ? mean : c;
    out_cent[idx] = 0.99f * c + 0.01f * nc;
}

extern "C" void kernel_launch(void* const* d_in, const int* in_sizes, int n_in,
                              void* d_out, int out_size) {
    const float* x = (const float*)d_in[0];
    const float* cent = (const float*)d_in[1];
    const int N = in_sizes[0] / FEAT;
    const int K = in_sizes[1] / FEAT;

    float* out = (float*)d_out;
    float* out_assign = nullptr;
    float* out_cent = nullptr;
    if (out_size == N + K * FEAT) {          // [assignments | updated centroids]
        out_assign = out;
        out_cent = out + N;
    } else if (out_size == K * FEAT) {       // centroids only
        out_cent = out;
    } else if (out_size == N) {              // assignments only
        out_assign = out;
    } else {                                  // best effort: concat layout
        out_assign = out;
        out_cent = out + N;
    }

    int init_total = K * FEAT;
    init_kernel<<<(init_total + 255) / 256, 256>>>(cent, K);
    assign_scatter_kernel<<<(N + 255) / 256, 256>>>(x, cent, out_assign, N, K);
    if (out_cent)
        finalize_kernel<<<(K * FEAT + 255) / 256, 256>>>(cent, out_cent, K);
}

// round 2
// speedup vs baseline: 1.0202x; 1.0202x over previous
#include <cuda_runtime.h>
#include <cuda_bf16.h>
#include <cstdint>

#define FEAT 64
#define KMAX 2048
#define CHUNK 128
#define GROUP 16
#define SSTRIDE 132   // 132*4 bytes per row, 16B-aligned rows and 16B-aligned 16-float groups

// Scratch (no allocations allowed): segment sums, counts, centroid norms.
__device__ float g_sums[KMAX * FEAT];
__device__ float g_counts[KMAX];
__device__ float g_cnorm[KMAX];

// ---- packed f32x2 helpers (Blackwell FFMA2 path) ----
__device__ __forceinline__ unsigned long long pack_dup(float v) {
    unsigned long long r;
    asm("mov.b64 %0, {%1, %1};" : "=l"(r) : "r"(__float_as_uint(v)));
    return r;
}
__device__ __forceinline__ unsigned long long fma2(unsigned long long a,
                                                   unsigned long long b,
                                                   unsigned long long c) {
    unsigned long long d;
    asm("fma.rn.f32x2 %0, %1, %2, %3;" : "=l"(d) : "l"(a), "l"(b), "l"(c));
    return d;
}
__device__ __forceinline__ void unpack2(unsigned long long p, float& lo, float& hi) {
    unsigned int a, b;
    asm("mov.b64 {%0, %1}, %2;" : "=r"(a), "=r"(b) : "l"(p));
    lo = __uint_as_float(a);
    hi = __uint_as_float(b);
}

// K0: zero scratch + compute ||c||^2
__global__ void init_kernel(const float* __restrict__ cent, int K) {
    int idx = blockIdx.x * blockDim.x + threadIdx.x;
    if (idx < K * FEAT) g_sums[idx] = 0.0f;
    if (idx < K) {
        g_counts[idx] = 0.0f;
        float s = 0.0f;
        const float4* row = reinterpret_cast<const float4*>(cent + (size_t)idx * FEAT);
#pragma unroll
        for (int q = 0; q < FEAT / 4; q++) {
            float4 v = row[q];
            s += v.x * v.x + v.y * v.y + v.z * v.z + v.w * v.w;
        }
        g_cnorm[idx] = s;
    }
}

// K1: assignment (argmin over K of ||c||^2 - 2 x.c) + fused scatter into g_sums/g_counts.
__global__ void __launch_bounds__(256, 2)
assign_scatter_kernel(const float* __restrict__ x,
                      const float* __restrict__ cent,
                      float* __restrict__ out_assign,  // may be null
                      int N, int K) {
    __shared__ float csm[FEAT * SSTRIDE];  // transposed chunk: csm[k*SSTRIDE + j]
    __shared__ float cnsm[CHUNK];

    const int i = blockIdx.x * 256 + threadIdx.x;

    // Load this thread's point into registers.
    float xr[FEAT];
    if (i < N) {
        const float4* xv = reinterpret_cast<const float4*>(x + (size_t)i * FEAT);
#pragma unroll
        for (int q = 0; q < FEAT / 4; q++) {
            float4 v = xv[q];
            xr[4 * q + 0] = v.x; xr[4 * q + 1] = v.y;
            xr[4 * q + 2] = v.z; xr[4 * q + 3] = v.w;
        }
    } else {
#pragma unroll
        for (int q = 0; q < FEAT; q++) xr[q] = 0.0f;
    }

    float best = 3.4e38f;
    int bestj = 0;

    for (int c0 = 0; c0 < K; c0 += CHUNK) {
        __syncthreads();
        // Coalesced global read, transposed shared write (4-way bank conflict, tiny loop).
        for (int idx = threadIdx.x; idx < CHUNK * FEAT; idx += 256) {
            int j = idx >> 6;        // centroid within chunk
            int k = idx & (FEAT - 1);
            csm[k * SSTRIDE + j] = cent[(size_t)(c0 + j) * FEAT + k];
        }
        if (threadIdx.x < CHUNK) cnsm[threadIdx.x] = g_cnorm[c0 + threadIdx.x];
        __syncthreads();

        // 16 centroids at a time; 8 packed f32x2 accumulators; shared loads
        // software-pipelined one k ahead so LDS latency is never exposed.
        for (int j = 0; j < CHUNK; j += GROUP) {
            unsigned long long acc[8];
#pragma unroll
            for (int t = 0; t < 8; t++) acc[t] = 0ull;

            const ulonglong2* r0 =
                reinterpret_cast<const ulonglong2*>(csm + 0 * SSTRIDE + j);
            ulonglong2 c0v = r0[0], c1v = r0[1], c2v = r0[2], c3v = r0[3];

#pragma unroll
            for (int k = 0; k < FEAT; k++) {
                ulonglong2 n0, n1, n2, n3;
                if (k + 1 < FEAT) {
                    const ulonglong2* rn =
                        reinterpret_cast<const ulonglong2*>(csm + (k + 1) * SSTRIDE + j);
                    n0 = rn[0]; n1 = rn[1]; n2 = rn[2]; n3 = rn[3];
                }
                unsigned long long xp = pack_dup(xr[k]);
                acc[0] = fma2(xp, c0v.x, acc[0]);
                acc[1] = fma2(xp, c0v.y, acc[1]);
                acc[2] = fma2(xp, c1v.x, acc[2]);
                acc[3] = fma2(xp, c1v.y, acc[3]);
                acc[4] = fma2(xp, c2v.x, acc[4]);
                acc[5] = fma2(xp, c2v.y, acc[5]);
                acc[6] = fma2(xp, c3v.x, acc[6]);
                acc[7] = fma2(xp, c3v.y, acc[7]);
                if (k + 1 < FEAT) { c0v = n0; c1v = n1; c2v = n2; c3v = n3; }
            }

            float d[16];
#pragma unroll
            for (int t = 0; t < 8; t++) unpack2(acc[t], d[2 * t], d[2 * t + 1]);
#pragma unroll
            for (int t = 0; t < GROUP; t++) {
                float score = cnsm[j + t] - 2.0f * d[t];
                if (score < best) { best = score; bestj = c0 + j + t; }
            }
        }
    }

    if (i < N) {
        if (out_assign) out_assign[i] = (float)bestj;
        // Fused scatter: x is already in registers.
        atomicAdd(&g_counts[bestj], 1.0f);
        float* srow = g_sums + (size_t)bestj * FEAT;
#pragma unroll
        for (int k = 0; k < FEAT; k++) atomicAdd(&srow[k], xr[k]);
    }
}

// K2: EMA update of centroids.
__global__ void finalize_kernel(const float* __restrict__ cent,
                                float* __restrict__ out_cent, int K) {
    int idx = blockIdx.x * blockDim.x + threadIdx.x;
    if (idx >= K * FEAT) return;
    int k = idx >> 6;
    float cnt = g_counts[k];
    float c = cent[idx];
    float mean = g_sums[idx] / fmaxf(cnt, 1.0f);
    float nc = (cnt > 0.0f) ? mean : c;
    out_cent[idx] = 0.99f * c + 0.01f * nc;
}

extern "C" void kernel_launch(void* const* d_in, const int* in_sizes, int n_in,
                              void* d_out, int out_size) {
    const float* x = (const float*)d_in[0];
    const float* cent = (const float*)d_in[1];
    const int N = in_sizes[0] / FEAT;
    const int K = in_sizes[1] / FEAT;

    float* out = (float*)d_out;
    float* out_assign = nullptr;
    float* out_cent = nullptr;
    if (out_size == N + K * FEAT) {          // [assignments | updated centroids]
        out_assign = out;
        out_cent = out + N;
    } else if (out_size == K * FEAT) {       // centroids only
        out_cent = out;
    } else if (out_size == N) {              // assignments only
        out_assign = out;
    } else {                                  // best effort: concat layout
        out_assign = out;
        out_cent = out + N;
    }

    int init_total = K * FEAT;
    init_kernel<<<(init_total + 255) / 256, 256>>>(cent, K);
    assign_scatter_kernel<<<(N + 255) / 256, 256>>>(x, cent, out_assign, N, K);
    if (out_cent)
        finalize_kernel<<<(K * FEAT + 255) / 256, 256>>>(cent, out_cent, K);
}

// round 4
// speedup vs baseline: 2.0736x; 2.0325x over previous
#include <cuda_runtime.h>
#include <cuda_bf16.h>
#include <cstdint>

#define FEAT 64
#define KMAX 2048
#define NCH 128          // centroids per SMEM chunk
#define CTA_PTS 256      // points per CTA (8 warps x 32)

// ---------------- scratch (no allocations allowed) ----------------
__device__ float g_sums[KMAX * FEAT];
__device__ float g_counts[KMAX];
__device__ float g_cnorm[KMAX];
__device__ __nv_bfloat16 g_chi[KMAX * FEAT];
__device__ __nv_bfloat16 g_cmid[KMAX * FEAT];
__device__ __nv_bfloat16 g_clo[KMAX * FEAT];

// ---------------- helpers ----------------
__device__ __forceinline__ uint32_t smem_u32(const void* p) {
    uint32_t a;
    asm("{ .reg .u64 t; cvta.to.shared.u64 t, %1; cvt.u32.u64 %0, t; }"
        : "=r"(a) : "l"(p));
    return a;
}
__device__ __forceinline__ void split3(float x, __nv_bfloat16& h,
                                       __nv_bfloat16& m, __nv_bfloat16& l) {
    h = __float2bfloat16(x);
    float r1 = x - __bfloat162float(h);
    m = __float2bfloat16(r1);
    float r2 = r1 - __bfloat162float(m);
    l = __float2bfloat16(r2);
}
__device__ __forceinline__ uint32_t pack_bf2(__nv_bfloat16 a, __nv_bfloat16 b) {
    __nv_bfloat162 t = __halves2bfloat162(a, b);
    return *reinterpret_cast<uint32_t*>(&t);
}
__device__ __forceinline__ void ldsm_x4(uint32_t* r, uint32_t addr) {
    asm volatile("ldmatrix.sync.aligned.m8n8.x4.shared.b16 {%0,%1,%2,%3}, [%4];"
                 : "=r"(r[0]), "=r"(r[1]), "=r"(r[2]), "=r"(r[3]) : "r"(addr));
}
__device__ __forceinline__ void mma_bf16(float* d, const uint32_t* a,
                                         uint32_t b0, uint32_t b1) {
    asm volatile(
        "mma.sync.aligned.m16n8k16.row.col.f32.bf16.bf16.f32 "
        "{%0,%1,%2,%3},{%4,%5,%6,%7},{%8,%9},{%0,%1,%2,%3};"
        : "+f"(d[0]), "+f"(d[1]), "+f"(d[2]), "+f"(d[3])
        : "r"(a[0]), "r"(a[1]), "r"(a[2]), "r"(a[3]), "r"(b0), "r"(b1));
}

// ---------------- SMEM layout (dynamic) ----------------
// B buffers: 2 x (3 splits x 128 rows x 128B) = 98304
// cns (KMAX floats) at 98304 ; sidx (CTA_PTS ints) at 106496
#define SM_B      0
#define BUF_SZ    49152
#define SPL_SZ    16384
#define SM_CNS    98304
#define SM_SIDX   106496
#define SM_TOTAL  107520

// B swizzle: row n (128B), 16B chunk qc -> n*128 + ((qc ^ (n&7))<<4)
__device__ __forceinline__ uint32_t b_off(int n, int qc) {
    return (uint32_t)(n * 128 + (((qc ^ (n & 7)) & 7) << 4));
}

// K0: zero scratch, bf16-split centroids, compute ||c||^2
__global__ void prep_kernel(const float* __restrict__ cent, int K) {
    int idx = blockIdx.x * blockDim.x + threadIdx.x;
    if (idx < K * FEAT) {
        g_sums[idx] = 0.0f;
        float v = cent[idx];
        __nv_bfloat16 h, m, l;
        split3(v, h, m, l);
        g_chi[idx] = h; g_cmid[idx] = m; g_clo[idx] = l;
    }
    if (idx < K) {
        g_counts[idx] = 0.0f;
        float s = 0.0f;
        const float4* row = reinterpret_cast<const float4*>(cent + (size_t)idx * FEAT);
#pragma unroll
        for (int q = 0; q < FEAT / 4; q++) {
            float4 v = row[q];
            s += v.x * v.x + v.y * v.y + v.z * v.z + v.w * v.w;
        }
        g_cnorm[idx] = s;
    }
}

// K1: HMMA assignment + fused scatter
__global__ void __launch_bounds__(256, 1)
assign_kernel(const float* __restrict__ x,
              float* __restrict__ out_assign, int N, int K) {
    extern __shared__ char smem[];
    const uint32_t sb = smem_u32(smem);
    const int tid = threadIdx.x;
    const int lane = tid & 31;
    const int w = tid >> 5;
    float* cns = reinterpret_cast<float*>(smem + SM_CNS);
    int* sidx = reinterpret_cast<int*>(smem + SM_SIDX);

    // ---- A fragments: 2 Mtiles x 3 splits x 4 ksteps x 4 regs, resident ----
    uint32_t aH[2][4][4], aM[2][4][4], aL[2][4][4];
    const size_t pbase = (size_t)blockIdx.x * CTA_PTS + (size_t)w * 32;
#pragma unroll
    for (int mt = 0; mt < 2; mt++) {
#pragma unroll
        for (int rh = 0; rh < 2; rh++) {
            size_t row = pbase + mt * 16 + (lane >> 2) + rh * 8;
            if (row >= (size_t)N) row = (size_t)N - 1;
            const float* xr = x + row * FEAT + (lane & 3) * 2;
#pragma unroll
            for (int kc = 0; kc < 8; kc++) {
                float2 v = *reinterpret_cast<const float2*>(xr + kc * 8);
                __nv_bfloat16 hx, mx, lx, hy, my, ly;
                split3(v.x, hx, mx, lx);
                split3(v.y, hy, my, ly);
                int ks = kc >> 1;
                int ri = (kc & 1) * 2 + rh;
                aH[mt][ks][ri] = pack_bf2(hx, hy);
                aM[mt][ks][ri] = pack_bf2(mx, my);
                aL[mt][ks][ri] = pack_bf2(lx, ly);
            }
        }
    }

    // ---- cnorm -> shared ----
    for (int i = tid; i < K; i += 256) cns[i] = g_cnorm[i];

    const uint4* gsrc[3] = {
        reinterpret_cast<const uint4*>(g_chi),
        reinterpret_cast<const uint4*>(g_cmid),
        reinterpret_cast<const uint4*>(g_clo)};

    // ---- load chunk 0 into buf 0 ----
#pragma unroll
    for (int i = 0; i < 12; i++) {
        int idx = tid + i * 256;              // < 3072
        int s = idx >> 10;
        int rem = idx & 1023;
        int n = rem >> 3, qc = rem & 7;
        uint4 v = gsrc[s][(size_t)n * 8 + qc];
        *reinterpret_cast<uint4*>(smem + SM_B + s * SPL_SZ + b_off(n, qc)) = v;
    }
    __syncthreads();

    // running per-thread argmin: [mt][rowhalf]
    float bs[2][2] = {{3.4e38f, 3.4e38f}, {3.4e38f, 3.4e38f}};
    int bj[2][2] = {{0, 0}, {0, 0}};

    const int nchunk = K / NCH;
#pragma unroll 1
    for (int c = 0; c < nchunk; c++) {
        const int b = c & 1;
        const uint32_t bufb = sb + SM_B + b * BUF_SZ;
        const int c0 = c * NCH;

        // prefetch next chunk into registers (hidden under the MMAs)
        uint4 pre[12];
        const bool has = (c + 1) < nchunk;
        if (has) {
            const int nc0 = (c + 1) * NCH;
#pragma unroll
            for (int i = 0; i < 12; i++) {
                int idx = tid + i * 256;
                int s = idx >> 10;
                int rem = idx & 1023;
                int n = rem >> 3, qc = rem & 7;
                pre[i] = gsrc[s][(size_t)(nc0 + n) * 8 + qc];
            }
        }

        // ---- GEMM over 16 coltiles of 8 centroids ----
#pragma unroll 1
        for (int ct = 0; ct < NCH / 8; ct++) {
            const int n0 = ct * 8;
            const int n = n0 + (lane & 7);
            const int kc = lane >> 3;   // matrix index 0..3 (halves add +4)
            uint32_t bh[8], bm[8], bl[8];
#pragma unroll
            for (int h = 0; h < 2; h++) {
                uint32_t a0 = bufb + 0 * SPL_SZ + b_off(n, h * 4 + kc);
                uint32_t a1 = bufb + 1 * SPL_SZ + b_off(n, h * 4 + kc);
                uint32_t a2 = bufb + 2 * SPL_SZ + b_off(n, h * 4 + kc);
                ldsm_x4(bh + h * 4, a0);
                ldsm_x4(bm + h * 4, a1);
                ldsm_x4(bl + h * 4, a2);
            }

#pragma unroll
            for (int mt = 0; mt < 2; mt++) {
                float accA[4] = {0.f, 0.f, 0.f, 0.f};
                float accB[4] = {0.f, 0.f, 0.f, 0.f};
#pragma unroll
                for (int ks = 0; ks < 4; ks++) {
                    const int h4 = (ks >> 1) * 4 + (ks & 1) * 2;
                    const uint32_t bH0 = bh[h4], bH1 = bh[h4 + 1];
                    const uint32_t bM0 = bm[h4], bM1 = bm[h4 + 1];
                    const uint32_t bL0 = bl[h4], bL1 = bl[h4 + 1];
                    mma_bf16(accA, aH[mt][ks], bH0, bH1);
                    mma_bf16(accB, aH[mt][ks], bM0, bM1);
                    mma_bf16(accA, aM[mt][ks], bH0, bH1);
                    mma_bf16(accB, aM[mt][ks], bM0, bM1);
                    mma_bf16(accA, aL[mt][ks], bH0, bH1);
                    mma_bf16(accB, aH[mt][ks], bL0, bL1);
                }
                const int jb = c0 + n0 + (lane & 3) * 2;
                const float cn0 = cns[jb], cn1 = cns[jb + 1];
#pragma unroll
                for (int rh = 0; rh < 2; rh++) {
                    float d0 = accA[rh * 2] + accB[rh * 2];
                    float d1 = accA[rh * 2 + 1] + accB[rh * 2 + 1];
                    float s0 = fmaf(-2.0f, d0, cn0);
                    float s1 = fmaf(-2.0f, d1, cn1);
                    if (s0 < bs[mt][rh]) { bs[mt][rh] = s0; bj[mt][rh] = jb; }
                    if (s1 < bs[mt][rh]) { bs[mt][rh] = s1; bj[mt][rh] = jb + 1; }
                }
            }
        }

        // store prefetched chunk to the other buffer
        if (has) {
            char* dst = smem + SM_B + (b ^ 1) * BUF_SZ;
#pragma unroll
            for (int i = 0; i < 12; i++) {
                int idx = tid + i * 256;
                int s = idx >> 10;
                int rem = idx & 1023;
                int n = rem >> 3, qc = rem & 7;
                *reinterpret_cast<uint4*>(dst + s * SPL_SZ + b_off(n, qc)) = pre[i];
            }
        }
        __syncthreads();
    }

    // ---- cross-lane argmin within each quad (lanes sharing a row) ----
#pragma unroll
    for (int mt = 0; mt < 2; mt++) {
#pragma unroll
        for (int rh = 0; rh < 2; rh++) {
            float s = bs[mt][rh];
            int j = bj[mt][rh];
#pragma unroll
            for (int off = 1; off <= 2; off <<= 1) {
                float os = __shfl_xor_sync(0xffffffffu, s, off);
                int oj = __shfl_xor_sync(0xffffffffu, j, off);
                if (os < s || (os == s && oj < j)) { s = os; j = oj; }
            }
            if ((lane & 3) == 0) {
                int local = w * 32 + mt * 16 + (lane >> 2) + rh * 8;
                sidx[local] = j;
            }
        }
    }
    __syncthreads();

    // ---- output + fused scatter: one thread per point ----
    const size_t p = (size_t)blockIdx.x * CTA_PTS + tid;
    if (p < (size_t)N) {
        const int bestj = sidx[tid];
        if (out_assign) out_assign[p] = (float)bestj;
        atomicAdd(&g_counts[bestj], 1.0f);
        const float4* xr = reinterpret_cast<const float4*>(x + p * FEAT);
        float* srow = g_sums + (size_t)bestj * FEAT;
#pragma unroll
        for (int q = 0; q < FEAT / 4; q++) {
            float4 v = xr[q];
            atomicAdd(&srow[4 * q + 0], v.x);
            atomicAdd(&srow[4 * q + 1], v.y);
            atomicAdd(&srow[4 * q + 2], v.z);
            atomicAdd(&srow[4 * q + 3], v.w);
        }
    }
}

// K2: EMA update of centroids.
__global__ void finalize_kernel(const float* __restrict__ cent,
                                float* __restrict__ out_cent, int K) {
    int idx = blockIdx.x * blockDim.x + threadIdx.x;
    if (idx >= K * FEAT) return;
    int k = idx >> 6;
    float cnt = g_counts[k];
    float c = cent[idx];
    float mean = g_sums[idx] / fmaxf(cnt, 1.0f);
    float nc = (cnt > 0.0f) ? mean : c;
    out_cent[idx] = 0.99f * c + 0.01f * nc;
}

extern "C" void kernel_launch(void* const* d_in, const int* in_sizes, int n_in,
                              void* d_out, int out_size) {
    const float* x = (const float*)d_in[0];
    const float* cent = (const float*)d_in[1];
    const int N = in_sizes[0] / FEAT;
    const int K = in_sizes[1] / FEAT;

    float* out = (float*)d_out;
    float* out_assign = nullptr;
    float* out_cent = nullptr;
    if (out_size == N + K * FEAT) {
        out_assign = out;
        out_cent = out + N;
    } else if (out_size == K * FEAT) {
        out_cent = out;
    } else if (out_size == N) {
        out_assign = out;
    } else {
        out_assign = out;
        out_cent = out + N;
    }

    static int smem_set = 0;
    if (!smem_set) {
        cudaFuncSetAttribute(assign_kernel,
                             cudaFuncAttributeMaxDynamicSharedMemorySize, SM_TOTAL);
        smem_set = 1;
    }

    prep_kernel<<<(K * FEAT + 255) / 256, 256>>>(cent, K);
    assign_kernel<<<(N + CTA_PTS - 1) / CTA_PTS, 256, SM_TOTAL>>>(x, out_assign, N, K);
    if (out_cent)
        finalize_kernel<<<(K * FEAT + 255) / 256, 256>>>(cent, out_cent, K);
}